// round 2
// baseline (speedup 1.0000x reference)
#include <cuda_runtime.h>
#include <cuda_bf16.h>
#include <math.h>

// Problem constants
#define H 64
#define VOCAB 5
#define S 384
#define B 8
#define NROWS (B * S * S)            // 1,179,648 rows of h=64
#define TPB 128                       // threads (rows) per block
#define XBUF_STRIDE 65                // bank-conflict-free per-thread row buffer

// Dynamic shared memory layout (bytes)
//  sW[3][64*64]  : 3 * 16384 = 49152
//  sWo[64*5]     : 1280
//  sB[3][64]     : 768
//  sLNg[64]      : 256
//  sLNb[64]      : 256
//  sBo[8]        : 32 (padded)
//  xbuf[TPB*65]  : 33280
#define SMEM_W_OFF    0
#define SMEM_WO_OFF   (SMEM_W_OFF + 3 * H * H)
#define SMEM_B_OFF    (SMEM_WO_OFF + H * VOCAB)
#define SMEM_LNG_OFF  (SMEM_B_OFF + 3 * H)
#define SMEM_LNB_OFF  (SMEM_LNG_OFF + H)
#define SMEM_BO_OFF   (SMEM_LNB_OFF + H)
#define SMEM_XBUF_OFF (SMEM_BO_OFF + 8)
#define SMEM_FLOATS   (SMEM_XBUF_OFF + TPB * XBUF_STRIDE)
#define SMEM_BYTES    (SMEM_FLOATS * 4)

__global__ __launch_bounds__(TPB)
void fused_mlp_kernel(const float* __restrict__ x,
                      const float* __restrict__ W1, const float* __restrict__ b1,
                      const float* __restrict__ W2, const float* __restrict__ b2,
                      const float* __restrict__ W3, const float* __restrict__ b3,
                      const float* __restrict__ ln_g, const float* __restrict__ ln_b,
                      const float* __restrict__ Wo, const float* __restrict__ bo,
                      float* __restrict__ out)
{
    extern __shared__ float smem[];
    float* sW   = smem + SMEM_W_OFF;     // [3][64*64]
    float* sWo  = smem + SMEM_WO_OFF;    // [64*5]
    float* sB   = smem + SMEM_B_OFF;     // [3][64]
    float* sLNg = smem + SMEM_LNG_OFF;
    float* sLNb = smem + SMEM_LNB_OFF;
    float* sBo  = smem + SMEM_BO_OFF;
    float* xbuf = smem + SMEM_XBUF_OFF;  // [TPB][65]

    const int tid = threadIdx.x;

    // Cooperative weight/bias loads (all layers resident; no mid-kernel W swaps)
    for (int i = tid; i < H * H; i += TPB) {
        sW[0 * H * H + i] = W1[i];
        sW[1 * H * H + i] = W2[i];
        sW[2 * H * H + i] = W3[i];
    }
    for (int i = tid; i < H * VOCAB; i += TPB) sWo[i] = Wo[i];
    if (tid < H) {
        sB[0 * H + tid] = b1[tid];
        sB[1 * H + tid] = b2[tid];
        sB[2 * H + tid] = b3[tid];
        sLNg[tid] = ln_g[tid];
        sLNb[tid] = ln_b[tid];
    }
    if (tid < VOCAB) sBo[tid] = bo[tid];
    __syncthreads();

    const long long row = (long long)blockIdx.x * TPB + tid;
    if (row >= NROWS) return;

    float* myx = xbuf + tid * XBUF_STRIDE;

    // Load this row (256B, 16B-aligned) into the private shared scratch
    {
        const float4* xr = (const float4*)(x + row * H);
        #pragma unroll
        for (int i = 0; i < H / 4; i++) {
            float4 v = xr[i];
            myx[4 * i + 0] = v.x;
            myx[4 * i + 1] = v.y;
            myx[4 * i + 2] = v.z;
            myx[4 * i + 3] = v.w;
        }
    }

    // Three (Linear -> exact gelu -> LayerNorm) blocks
    #pragma unroll 1
    for (int layer = 0; layer < 3; layer++) {
        float acc[H];
        const float* bl = sB + layer * H;
        #pragma unroll
        for (int j = 0; j < H; j++) acc[j] = bl[j];

        const float4* Wl = (const float4*)(sW + layer * H * H);
        #pragma unroll 4
        for (int k = 0; k < H; k++) {
            const float xk = myx[k];
            #pragma unroll
            for (int j4 = 0; j4 < H / 4; j4++) {
                float4 w = Wl[k * (H / 4) + j4];   // broadcast across warp
                acc[4 * j4 + 0] = fmaf(xk, w.x, acc[4 * j4 + 0]);
                acc[4 * j4 + 1] = fmaf(xk, w.y, acc[4 * j4 + 1]);
                acc[4 * j4 + 2] = fmaf(xk, w.z, acc[4 * j4 + 2]);
                acc[4 * j4 + 3] = fmaf(xk, w.w, acc[4 * j4 + 3]);
            }
        }

        // exact gelu + LN statistics in registers
        float s = 0.0f, s2 = 0.0f;
        #pragma unroll
        for (int j = 0; j < H; j++) {
            float v = acc[j];
            float g = 0.5f * v * (1.0f + erff(v * 0.70710678118654752f));
            acc[j] = g;
            s  += g;
            s2 += g * g;
        }
        const float mu   = s * (1.0f / H);
        const float var  = s2 * (1.0f / H) - mu * mu;
        const float rstd = rsqrtf(var + 1e-5f);
        #pragma unroll
        for (int j = 0; j < H; j++) {
            myx[j] = (acc[j] - mu) * rstd * sLNg[j] + sLNb[j];
        }
    }

    // Final 64 -> 5 projection
    float o[VOCAB];
    #pragma unroll
    for (int v = 0; v < VOCAB; v++) o[v] = sBo[v];
    #pragma unroll 4
    for (int j = 0; j < H; j++) {
        const float hv = myx[j];
        #pragma unroll
        for (int v = 0; v < VOCAB; v++) {
            o[v] = fmaf(hv, sWo[j * VOCAB + v], o[v]);  // broadcast
        }
    }
    float* op = out + row * VOCAB;
    #pragma unroll
    for (int v = 0; v < VOCAB; v++) op[v] = o[v];
}

// In-place symmetrization: out[b,i,j,:] = out[b,j,i,:] = 0.5*(raw[b,i,j]+raw[b,j,i]).
// Each (b,i,j) with j>i is owned by exactly one thread; diagonal is a fixed point.
// Idempotent under graph replay (kernel 1 rewrites raw each replay anyway).
__global__ void symmetrize_kernel(float* __restrict__ out)
{
    int idx = blockIdx.x * blockDim.x + threadIdx.x;
    if (idx >= NROWS) return;
    int j = idx % S;
    int t = idx / S;
    int i = t % S;
    int b = t / S;
    if (j <= i) return;

    float* p = out + (size_t)idx * VOCAB;
    float* q = out + ((size_t)(b * S + j) * S + i) * VOCAB;
    #pragma unroll
    for (int v = 0; v < VOCAB; v++) {
        float m = 0.5f * (p[v] + q[v]);
        p[v] = m;
        q[v] = m;
    }
}

extern "C" void kernel_launch(void* const* d_in, const int* in_sizes, int n_in,
                              void* d_out, int out_size)
{
    const float* x    = (const float*)d_in[0];
    const float* W1   = (const float*)d_in[1];
    const float* b1   = (const float*)d_in[2];
    const float* W2   = (const float*)d_in[3];
    const float* b2   = (const float*)d_in[4];
    const float* W3   = (const float*)d_in[5];
    const float* b3   = (const float*)d_in[6];
    const float* ln_g = (const float*)d_in[7];
    const float* ln_b = (const float*)d_in[8];
    const float* Wo   = (const float*)d_in[9];
    const float* bo   = (const float*)d_in[10];
    float* out = (float*)d_out;

    static bool attr_set = false;
    if (!attr_set) {
        cudaFuncSetAttribute(fused_mlp_kernel,
                             cudaFuncAttributeMaxDynamicSharedMemorySize, SMEM_BYTES);
        attr_set = true;
    }

    const int grid1 = (NROWS + TPB - 1) / TPB;   // 9216
    fused_mlp_kernel<<<grid1, TPB, SMEM_BYTES>>>(x, W1, b1, W2, b2, W3, b3,
                                                 ln_g, ln_b, Wo, bo, out);

    const int tpb2 = 256;
    const int grid2 = (NROWS + tpb2 - 1) / tpb2;
    symmetrize_kernel<<<grid2, tpb2>>>(out);
}

// round 4
// speedup vs baseline: 2.0576x; 2.0576x over previous
#include <cuda_runtime.h>
#include <cuda_bf16.h>
#include <math.h>
#include <stdint.h>

#define H 64
#define VOCAB 5
#define S 384
#define BATCH 8
#define NROWS (BATCH * S * S)     // 1,179,648
#define NTILES (NROWS / 128)      // 9216 tiles of 128 rows (32 per warp)
#define TPB 128
#define GRID_MAIN 444

// ---- dynamic smem layout (floats/bytes) ----
// sBF  [3][2][4][8][32] uint2  : 49152 B   (W fragments: layer, hi/lo, kstep, ntile, lane)
// sWo8 [64][8] float           : 2048 B    (Wo padded rows)
// sBias[3][64] float           : 768 B
// sLNg [64], sLNb[64]          : 512 B
#define SM_BF    0
#define SM_WO8   49152
#define SM_BIAS  (SM_WO8 + 2048)
#define SM_LNG   (SM_BIAS + 768)
#define SM_LNB   (SM_LNG + 256)
#define SMEM_BYTES (SM_LNB + 256)   // 52480

// Pre-built B fragments for mma.m16n8k16.row.col: element (k,n):
//   b0 = {W[k0][n], W[k0+1][n]},  b1 = {W[k0+8][n], W[k0+9][n]},
//   k0 = ks*16 + (lane%4)*2, n = nt*8 + lane/4
__device__ uint2 g_bf[3][2][4][8][32];

static __device__ __forceinline__ unsigned short bfu(__nv_bfloat16 h) {
    return __bfloat16_as_ushort(h);
}

__global__ void prep_weights(const float* __restrict__ W1, const float* __restrict__ W2,
                             const float* __restrict__ W3) {
    int idx = blockIdx.x * blockDim.x + threadIdx.x;
    if (idx >= 3 * 2 * 4 * 8 * 32) return;
    int lane = idx & 31;
    int nt = (idx >> 5) & 7;
    int ks = (idx >> 8) & 3;
    int t  = (idx >> 10) & 1;
    int l  = idx >> 11;
    const float* W = (l == 0) ? W1 : (l == 1) ? W2 : W3;
    int n  = nt * 8 + (lane >> 2);
    int k0 = ks * 16 + (lane & 3) * 2;

    unsigned short e[4];
    int kk[4] = {k0, k0 + 1, k0 + 8, k0 + 9};
    for (int i = 0; i < 4; i++) {
        float w = W[kk[i] * H + n];
        __nv_bfloat16 hi = __float2bfloat16_rn(w);
        if (t == 0) e[i] = bfu(hi);
        else        e[i] = bfu(__float2bfloat16_rn(w - __bfloat162float(hi)));
    }
    uint2 r;
    r.x = (uint32_t)e[0] | ((uint32_t)e[1] << 16);
    r.y = (uint32_t)e[2] | ((uint32_t)e[3] << 16);
    g_bf[l][t][ks][nt][lane] = r;
}

// hi/lo bf16 split of a float pair, packed as bf16x2 (low = first arg)
static __device__ __forceinline__ void splitpk(float a, float b, uint32_t& hp, uint32_t& lp) {
    __nv_bfloat16 ha = __float2bfloat16_rn(a);
    __nv_bfloat16 hb = __float2bfloat16_rn(b);
    __nv_bfloat16 la = __float2bfloat16_rn(a - __bfloat162float(ha));
    __nv_bfloat16 lb = __float2bfloat16_rn(b - __bfloat162float(hb));
    hp = (uint32_t)bfu(ha) | ((uint32_t)bfu(hb) << 16);
    lp = (uint32_t)bfu(la) | ((uint32_t)bfu(lb) << 16);
}

#define MMA(d, a, bx, by)                                                              \
    asm volatile("mma.sync.aligned.m16n8k16.row.col.f32.bf16.bf16.f32 "                \
        "{%0,%1,%2,%3}, {%4,%5,%6,%7}, {%8,%9}, {%0,%1,%2,%3};"                        \
        : "+f"(d[0]), "+f"(d[1]), "+f"(d[2]), "+f"(d[3])                               \
        : "r"(a[0]), "r"(a[1]), "r"(a[2]), "r"(a[3]), "r"(bx), "r"(by))

__global__ __launch_bounds__(TPB, 2)
void mma_mlp_kernel(const float* __restrict__ x,
                    const float* __restrict__ b1, const float* __restrict__ b2,
                    const float* __restrict__ b3,
                    const float* __restrict__ ln_g, const float* __restrict__ ln_b,
                    const float* __restrict__ Wo, const float* __restrict__ bo,
                    float* __restrict__ out) {
    extern __shared__ __align__(16) unsigned char smem[];
    uint2*  sBF   = (uint2*)(smem + SM_BF);     // [3][2][4][8][32]
    float*  sWo8  = (float*)(smem + SM_WO8);
    float*  sBias = (float*)(smem + SM_BIAS);
    float*  sLNg  = (float*)(smem + SM_LNG);
    float*  sLNb  = (float*)(smem + SM_LNB);

    const int tid  = threadIdx.x;
    const int lane = tid & 31;
    const int warp = tid >> 5;
    const int q    = lane >> 2;      // row-in-8
    const int tq   = lane & 3;       // col-quad

    // prologue
    {
        const uint4* src = (const uint4*)g_bf;
        uint4* dst = (uint4*)(smem + SM_BF);
        #pragma unroll
        for (int i = tid; i < 49152 / 16; i += TPB) dst[i] = src[i];
    }
    for (int i = tid; i < H * 8; i += TPB) {
        int c = i >> 3, v = i & 7;
        sWo8[i] = (v < VOCAB) ? Wo[c * VOCAB + v] : 0.0f;
    }
    if (tid < H) {
        sBias[tid] = b1[tid]; sBias[64 + tid] = b2[tid]; sBias[128 + tid] = b3[tid];
        sLNg[tid] = ln_g[tid]; sLNb[tid] = ln_b[tid];
    }
    __syncthreads();

    const float bo0 = bo[0], bo1 = bo[1], bo2 = bo[2], bo3 = bo[3], bo4 = bo[4];

    for (int tile = blockIdx.x; tile < NTILES; tile += gridDim.x) {
        const int rowbase = tile * 128 + warp * 32;
        const float* xb = x + (size_t)rowbase * H;

        // ---- load x directly into A fragments (hi/lo bf16 split) ----
        uint32_t ahi[2][4][4], alo[2][4][4];
        #pragma unroll
        for (int mt = 0; mt < 2; mt++)
            #pragma unroll
            for (int kc = 0; kc < 4; kc++)
                #pragma unroll
                for (int h2 = 0; h2 < 2; h2++)
                    #pragma unroll
                    for (int rr = 0; rr < 2; rr++) {
                        const float2 v = *(const float2*)(xb + (size_t)(mt * 16 + q + 8 * rr) * H
                                                          + kc * 16 + h2 * 8 + tq * 2);
                        splitpk(v.x, v.y, ahi[mt][kc][h2 * 2 + rr], alo[mt][kc][h2 * 2 + rr]);
                    }

        float acc[2][8][4];
        #pragma unroll
        for (int l = 0; l < 3; l++) {
            // init accumulators with bias (cols only depend on nt, i&1)
            #pragma unroll
            for (int nt = 0; nt < 8; nt++) {
                const float2 bb = *(const float2*)(sBias + l * 64 + nt * 8 + tq * 2);
                #pragma unroll
                for (int mt = 0; mt < 2; mt++) {
                    acc[mt][nt][0] = bb.x; acc[mt][nt][1] = bb.y;
                    acc[mt][nt][2] = bb.x; acc[mt][nt][3] = bb.y;
                }
            }
            // GEMM: 3-term bf16 split
            #pragma unroll
            for (int ks = 0; ks < 4; ks++) {
                #pragma unroll
                for (int nt = 0; nt < 8; nt++) {
                    const uint2 bh = sBF[(((l * 2 + 0) * 4 + ks) * 8 + nt) * 32 + lane];
                    const uint2 bl = sBF[(((l * 2 + 1) * 4 + ks) * 8 + nt) * 32 + lane];
                    MMA(acc[0][nt], ahi[0][ks], bh.x, bh.y);
                    MMA(acc[1][nt], ahi[1][ks], bh.x, bh.y);
                    MMA(acc[0][nt], alo[0][ks], bh.x, bh.y);
                    MMA(acc[1][nt], alo[1][ks], bh.x, bh.y);
                    MMA(acc[0][nt], ahi[0][ks], bl.x, bl.y);
                    MMA(acc[1][nt], ahi[1][ks], bl.x, bl.y);
                }
            }

            // ---- gelu (exact) + LN over the 64 cols of each row ----
            float s0[2][2] = {{0, 0}, {0, 0}}, s1[2][2] = {{0, 0}, {0, 0}};
            #pragma unroll
            for (int mt = 0; mt < 2; mt++)
                #pragma unroll
                for (int nt = 0; nt < 8; nt++)
                    #pragma unroll
                    for (int i = 0; i < 4; i++) {
                        float v = acc[mt][nt][i];
                        float g = 0.5f * v * (1.0f + erff(v * 0.70710678118654752f));
                        acc[mt][nt][i] = g;
                        s0[mt][i >> 1] += g;
                        s1[mt][i >> 1] += g * g;
                    }
            float mu[2][2], rs[2][2];
            #pragma unroll
            for (int mt = 0; mt < 2; mt++)
                #pragma unroll
                for (int rr = 0; rr < 2; rr++) {
                    float a = s0[mt][rr], b = s1[mt][rr];
                    a += __shfl_xor_sync(0xFFFFFFFF, a, 1);
                    b += __shfl_xor_sync(0xFFFFFFFF, b, 1);
                    a += __shfl_xor_sync(0xFFFFFFFF, a, 2);
                    b += __shfl_xor_sync(0xFFFFFFFF, b, 2);
                    const float m = a * (1.0f / 64.0f);
                    const float var = b * (1.0f / 64.0f) - m * m;
                    mu[mt][rr] = m;
                    rs[mt][rr] = rsqrtf(var + 1e-5f);
                }
            #pragma unroll
            for (int nt = 0; nt < 8; nt++) {
                const float2 gg = *(const float2*)(sLNg + nt * 8 + tq * 2);
                const float2 be = *(const float2*)(sLNb + nt * 8 + tq * 2);
                #pragma unroll
                for (int mt = 0; mt < 2; mt++)
                    #pragma unroll
                    for (int i = 0; i < 4; i++) {
                        const int rr = i >> 1;
                        const float ge = (i & 1) ? gg.y : gg.x;
                        const float bb = (i & 1) ? be.y : be.x;
                        acc[mt][nt][i] = (acc[mt][nt][i] - mu[mt][rr]) * rs[mt][rr] * ge + bb;
                    }
            }

            if (l < 2) {
                // rebuild A fragments from accumulators (D-frag == A-frag layout!)
                #pragma unroll
                for (int mt = 0; mt < 2; mt++)
                    #pragma unroll
                    for (int kc = 0; kc < 4; kc++) {
                        splitpk(acc[mt][2 * kc][0],     acc[mt][2 * kc][1],     ahi[mt][kc][0], alo[mt][kc][0]);
                        splitpk(acc[mt][2 * kc][2],     acc[mt][2 * kc][3],     ahi[mt][kc][1], alo[mt][kc][1]);
                        splitpk(acc[mt][2 * kc + 1][0], acc[mt][2 * kc + 1][1], ahi[mt][kc][2], alo[mt][kc][2]);
                        splitpk(acc[mt][2 * kc + 1][2], acc[mt][2 * kc + 1][3], ahi[mt][kc][3], alo[mt][kc][3]);
                    }
            }
        }

        // ---- final 64 -> 5 projection (quad-partial + butterfly reduce) ----
        float o[2][2][VOCAB];
        #pragma unroll
        for (int mt = 0; mt < 2; mt++)
            #pragma unroll
            for (int rr = 0; rr < 2; rr++) {
                o[mt][rr][0] = bo0; o[mt][rr][1] = bo1; o[mt][rr][2] = bo2;
                o[mt][rr][3] = bo3; o[mt][rr][4] = bo4;
            }
        #pragma unroll
        for (int nt = 0; nt < 8; nt++) {
            const int c0 = nt * 8 + tq * 2;
            const float4 wa = *(const float4*)(sWo8 + c0 * 8);
            const float  wa4 = sWo8[c0 * 8 + 4];
            const float4 wb = *(const float4*)(sWo8 + (c0 + 1) * 8);
            const float  wb4 = sWo8[(c0 + 1) * 8 + 4];
            #pragma unroll
            for (int mt = 0; mt < 2; mt++)
                #pragma unroll
                for (int rr = 0; rr < 2; rr++) {
                    const float h0 = acc[mt][nt][2 * rr], h1 = acc[mt][nt][2 * rr + 1];
                    o[mt][rr][0] = fmaf(h0, wa.x, fmaf(h1, wb.x, o[mt][rr][0]));
                    o[mt][rr][1] = fmaf(h0, wa.y, fmaf(h1, wb.y, o[mt][rr][1]));
                    o[mt][rr][2] = fmaf(h0, wa.z, fmaf(h1, wb.z, o[mt][rr][2]));
                    o[mt][rr][3] = fmaf(h0, wa.w, fmaf(h1, wb.w, o[mt][rr][3]));
                    o[mt][rr][4] = fmaf(h0, wa4,  fmaf(h1, wb4,  o[mt][rr][4]));
                }
        }
        #pragma unroll
        for (int mt = 0; mt < 2; mt++)
            #pragma unroll
            for (int rr = 0; rr < 2; rr++) {
                #pragma unroll
                for (int v = 0; v < VOCAB; v++) {
                    float t = o[mt][rr][v];
                    t += __shfl_xor_sync(0xFFFFFFFF, t, 1);
                    t += __shfl_xor_sync(0xFFFFFFFF, t, 2);
                    o[mt][rr][v] = t;
                }
                const int row = rowbase + mt * 16 + q + 8 * rr;
                float* op = out + (size_t)row * VOCAB;
                const float val = (tq & 2) ? ((tq & 1) ? o[mt][rr][3] : o[mt][rr][2])
                                           : ((tq & 1) ? o[mt][rr][1] : o[mt][rr][0]);
                op[tq] = val;
                if (tq == 0) op[4] = o[mt][rr][4];
            }
    }
}

// ---- tiled symmetrization: out = 0.5*(out + out^T) over (i,j), per batch ----
#define NT (S / 32)
#define TROW 160
#define TPAD 165
__global__ void symmetrize_tiled(float* __restrict__ out) {
    __shared__ float sA[32 * TPAD];
    __shared__ float sBt[32 * TPAD];
    int tp = blockIdx.x;
    const int b = blockIdx.y;
    int ti = 0;
    while (tp >= NT - ti) { tp -= NT - ti; ti++; }
    const int tj = ti + tp;
    const int bi = ti * 32, bj = tj * 32;
    const int tid = threadIdx.x;

    for (int f = tid; f < 32 * TROW; f += 256) {
        int r = f / TROW, c = f % TROW;
        sA [r * TPAD + c] = out[((size_t)(b * S + bi + r) * S + bj) * VOCAB + c];
        sBt[r * TPAD + c] = out[((size_t)(b * S + bj + r) * S + bi) * VOCAB + c];
    }
    __syncthreads();
    for (int f = tid; f < 32 * TROW; f += 256) {
        int r = f / TROW, c = f % TROW;
        int jj = c / VOCAB, v = c % VOCAB;
        float m = 0.5f * (sA[r * TPAD + c] + sBt[jj * TPAD + r * VOCAB + v]);
        out[((size_t)(b * S + bi + r) * S + bj) * VOCAB + c] = m;
    }
    for (int f = tid; f < 32 * TROW; f += 256) {
        int r = f / TROW, c = f % TROW;
        int jj = c / VOCAB, v = c % VOCAB;
        float m = 0.5f * (sBt[r * TPAD + c] + sA[jj * TPAD + r * VOCAB + v]);
        out[((size_t)(b * S + bj + r) * S + bi) * VOCAB + c] = m;
    }
}

extern "C" void kernel_launch(void* const* d_in, const int* in_sizes, int n_in,
                              void* d_out, int out_size) {
    const float* x    = (const float*)d_in[0];
    const float* W1   = (const float*)d_in[1];
    const float* b1   = (const float*)d_in[2];
    const float* W2   = (const float*)d_in[3];
    const float* b2   = (const float*)d_in[4];
    const float* W3   = (const float*)d_in[5];
    const float* b3   = (const float*)d_in[6];
    const float* ln_g = (const float*)d_in[7];
    const float* ln_b = (const float*)d_in[8];
    const float* Wo   = (const float*)d_in[9];
    const float* bo   = (const float*)d_in[10];
    float* out = (float*)d_out;

    static bool attr_set = false;
    if (!attr_set) {
        cudaFuncSetAttribute(mma_mlp_kernel,
                             cudaFuncAttributeMaxDynamicSharedMemorySize, SMEM_BYTES);
        attr_set = true;
    }

    prep_weights<<<(3 * 2 * 4 * 8 * 32 + 255) / 256, 256>>>(W1, W2, W3);
    mma_mlp_kernel<<<GRID_MAIN, TPB, SMEM_BYTES>>>(x, b1, b2, b3, ln_g, ln_b, Wo, bo, out);

    dim3 gsym(NT * (NT + 1) / 2, BATCH);
    symmetrize_tiled<<<gsym, 256>>>(out);
}

// round 5
// speedup vs baseline: 2.8716x; 1.3956x over previous
#include <cuda_runtime.h>
#include <cuda_bf16.h>
#include <math.h>
#include <stdint.h>

#define H 64
#define VOCAB 5
#define S 384
#define BATCH 8
#define NROWS (BATCH * S * S)     // 1,179,648
#define NTILES (NROWS / 128)      // 9216 tiles of 128 rows (32 per warp)
#define TPB 128
#define GRID_MAIN 296             // 148 SMs * 2 resident CTAs (clean persistent wave)

// ---- dynamic smem layout ----
#define SM_BF    0
#define SM_WO8   49152
#define SM_BIAS  (SM_WO8 + 2048)
#define SM_LNG   (SM_BIAS + 768)
#define SM_LNB   (SM_LNG + 256)
#define SMEM_BYTES (SM_LNB + 256)   // 52480

// Pre-built B fragments for mma.m16n8k16.row.col
__device__ uint2 g_bf[3][2][4][8][32];

static __device__ __forceinline__ unsigned short bfu(__nv_bfloat16 h) {
    return __bfloat16_as_ushort(h);
}

__global__ void prep_weights(const float* __restrict__ W1, const float* __restrict__ W2,
                             const float* __restrict__ W3) {
    int idx = blockIdx.x * blockDim.x + threadIdx.x;
    if (idx >= 3 * 2 * 4 * 8 * 32) return;
    int lane = idx & 31;
    int nt = (idx >> 5) & 7;
    int ks = (idx >> 8) & 3;
    int t  = (idx >> 10) & 1;
    int l  = idx >> 11;
    const float* W = (l == 0) ? W1 : (l == 1) ? W2 : W3;
    int n  = nt * 8 + (lane >> 2);
    int k0 = ks * 16 + (lane & 3) * 2;

    unsigned short e[4];
    int kk[4] = {k0, k0 + 1, k0 + 8, k0 + 9};
    for (int i = 0; i < 4; i++) {
        float w = W[kk[i] * H + n];
        __nv_bfloat16 hi = __float2bfloat16_rn(w);
        if (t == 0) e[i] = bfu(hi);
        else        e[i] = bfu(__float2bfloat16_rn(w - __bfloat162float(hi)));
    }
    uint2 r;
    r.x = (uint32_t)e[0] | ((uint32_t)e[1] << 16);
    r.y = (uint32_t)e[2] | ((uint32_t)e[3] << 16);
    g_bf[l][t][ks][nt][lane] = r;
}

static __device__ __forceinline__ void splitpk(float a, float b, uint32_t& hp, uint32_t& lp) {
    __nv_bfloat16 ha = __float2bfloat16_rn(a);
    __nv_bfloat16 hb = __float2bfloat16_rn(b);
    __nv_bfloat16 la = __float2bfloat16_rn(a - __bfloat162float(ha));
    __nv_bfloat16 lb = __float2bfloat16_rn(b - __bfloat162float(hb));
    hp = (uint32_t)bfu(ha) | ((uint32_t)bfu(hb) << 16);
    lp = (uint32_t)bfu(la) | ((uint32_t)bfu(lb) << 16);
}

// Branch-free exact-gelu: Abramowitz-Stegun 7.1.26 erf (abs err <= 1.5e-7),
// 1 MUFU.RCP + 1 MUFU.EX2, no divergence, no slow path.
static __device__ __forceinline__ float gelu_f(float v) {
    const float z  = fabsf(v) * 0.70710678118654752f;
    const float t  = __fdividef(1.0f, fmaf(0.3275911f, z, 1.0f));
    float p = fmaf(1.061405429f, t, -1.453152027f);
    p = fmaf(p, t, 1.421413741f);
    p = fmaf(p, t, -0.284496736f);
    p = fmaf(p, t, 0.254829592f);
    p = p * t;
    const float e  = __expf(-z * z);
    const float er = fmaf(-p, e, 1.0f);           // erf(|v|/sqrt2)
    const float es = copysignf(er, v);
    const float hv = 0.5f * v;
    return fmaf(hv, es, hv);
}

#define MMA(d, a, bx, by)                                                              \
    asm volatile("mma.sync.aligned.m16n8k16.row.col.f32.bf16.bf16.f32 "                \
        "{%0,%1,%2,%3}, {%4,%5,%6,%7}, {%8,%9}, {%0,%1,%2,%3};"                        \
        : "+f"(d[0]), "+f"(d[1]), "+f"(d[2]), "+f"(d[3])                               \
        : "r"(a[0]), "r"(a[1]), "r"(a[2]), "r"(a[3]), "r"(bx), "r"(by))

__global__ __launch_bounds__(TPB, 2)
void mma_mlp_kernel(const float* __restrict__ x,
                    const float* __restrict__ b1, const float* __restrict__ b2,
                    const float* __restrict__ b3,
                    const float* __restrict__ ln_g, const float* __restrict__ ln_b,
                    const float* __restrict__ Wo, const float* __restrict__ bo,
                    float* __restrict__ out) {
    extern __shared__ __align__(16) unsigned char smem[];
    uint2*  sBF   = (uint2*)(smem + SM_BF);
    float*  sWo8  = (float*)(smem + SM_WO8);
    float*  sBias = (float*)(smem + SM_BIAS);
    float*  sLNg  = (float*)(smem + SM_LNG);
    float*  sLNb  = (float*)(smem + SM_LNB);

    const int tid  = threadIdx.x;
    const int lane = tid & 31;
    const int warp = tid >> 5;
    const int q    = lane >> 2;
    const int tq   = lane & 3;

    {
        const uint4* src = (const uint4*)g_bf;
        uint4* dst = (uint4*)(smem + SM_BF);
        #pragma unroll
        for (int i = tid; i < 49152 / 16; i += TPB) dst[i] = src[i];
    }
    for (int i = tid; i < H * 8; i += TPB) {
        int c = i >> 3, v = i & 7;
        sWo8[i] = (v < VOCAB) ? Wo[c * VOCAB + v] : 0.0f;
    }
    if (tid < H) {
        sBias[tid] = b1[tid]; sBias[64 + tid] = b2[tid]; sBias[128 + tid] = b3[tid];
        sLNg[tid] = ln_g[tid]; sLNb[tid] = ln_b[tid];
    }
    __syncthreads();

    const float bo0 = bo[0], bo1 = bo[1], bo2 = bo[2], bo3 = bo[3], bo4 = bo[4];

    for (int tile = blockIdx.x; tile < NTILES; tile += gridDim.x) {
        const int rowbase = tile * 128 + warp * 32;
        const float* xb = x + (size_t)rowbase * H;

        uint32_t ahi[2][4][4], alo[2][4][4];
        #pragma unroll
        for (int mt = 0; mt < 2; mt++)
            #pragma unroll
            for (int kc = 0; kc < 4; kc++)
                #pragma unroll
                for (int h2 = 0; h2 < 2; h2++)
                    #pragma unroll
                    for (int rr = 0; rr < 2; rr++) {
                        const float2 v = *(const float2*)(xb + (size_t)(mt * 16 + q + 8 * rr) * H
                                                          + kc * 16 + h2 * 8 + tq * 2);
                        splitpk(v.x, v.y, ahi[mt][kc][h2 * 2 + rr], alo[mt][kc][h2 * 2 + rr]);
                    }

        float acc[2][8][4];
        #pragma unroll
        for (int l = 0; l < 3; l++) {
            #pragma unroll
            for (int nt = 0; nt < 8; nt++) {
                const float2 bb = *(const float2*)(sBias + l * 64 + nt * 8 + tq * 2);
                #pragma unroll
                for (int mt = 0; mt < 2; mt++) {
                    acc[mt][nt][0] = bb.x; acc[mt][nt][1] = bb.y;
                    acc[mt][nt][2] = bb.x; acc[mt][nt][3] = bb.y;
                }
            }
            #pragma unroll
            for (int ks = 0; ks < 4; ks++) {
                #pragma unroll
                for (int nt = 0; nt < 8; nt++) {
                    const uint2 bh = sBF[(((l * 2 + 0) * 4 + ks) * 8 + nt) * 32 + lane];
                    const uint2 bl = sBF[(((l * 2 + 1) * 4 + ks) * 8 + nt) * 32 + lane];
                    MMA(acc[0][nt], ahi[0][ks], bh.x, bh.y);
                    MMA(acc[1][nt], ahi[1][ks], bh.x, bh.y);
                    MMA(acc[0][nt], alo[0][ks], bh.x, bh.y);
                    MMA(acc[1][nt], alo[1][ks], bh.x, bh.y);
                    MMA(acc[0][nt], ahi[0][ks], bl.x, bl.y);
                    MMA(acc[1][nt], ahi[1][ks], bl.x, bl.y);
                }
            }

            // gelu (branch-free) + LN
            float s0[2][2] = {{0, 0}, {0, 0}}, s1[2][2] = {{0, 0}, {0, 0}};
            #pragma unroll
            for (int mt = 0; mt < 2; mt++)
                #pragma unroll
                for (int nt = 0; nt < 8; nt++)
                    #pragma unroll
                    for (int i = 0; i < 4; i++) {
                        const float g = gelu_f(acc[mt][nt][i]);
                        acc[mt][nt][i] = g;
                        s0[mt][i >> 1] += g;
                        s1[mt][i >> 1] += g * g;
                    }
            float mu[2][2], rs[2][2];
            #pragma unroll
            for (int mt = 0; mt < 2; mt++)
                #pragma unroll
                for (int rr = 0; rr < 2; rr++) {
                    float a = s0[mt][rr], b = s1[mt][rr];
                    a += __shfl_xor_sync(0xFFFFFFFF, a, 1);
                    b += __shfl_xor_sync(0xFFFFFFFF, b, 1);
                    a += __shfl_xor_sync(0xFFFFFFFF, a, 2);
                    b += __shfl_xor_sync(0xFFFFFFFF, b, 2);
                    const float m = a * (1.0f / 64.0f);
                    const float var = b * (1.0f / 64.0f) - m * m;
                    mu[mt][rr] = m;
                    rs[mt][rr] = rsqrtf(var + 1e-5f);
                }
            #pragma unroll
            for (int nt = 0; nt < 8; nt++) {
                const float2 gg = *(const float2*)(sLNg + nt * 8 + tq * 2);
                const float2 be = *(const float2*)(sLNb + nt * 8 + tq * 2);
                #pragma unroll
                for (int mt = 0; mt < 2; mt++)
                    #pragma unroll
                    for (int i = 0; i < 4; i++) {
                        const int rr = i >> 1;
                        const float ge = (i & 1) ? gg.y : gg.x;
                        const float bb = (i & 1) ? be.y : be.x;
                        acc[mt][nt][i] = (acc[mt][nt][i] - mu[mt][rr]) * rs[mt][rr] * ge + bb;
                    }
            }

            if (l < 2) {
                #pragma unroll
                for (int mt = 0; mt < 2; mt++)
                    #pragma unroll
                    for (int kc = 0; kc < 4; kc++) {
                        splitpk(acc[mt][2 * kc][0],     acc[mt][2 * kc][1],     ahi[mt][kc][0], alo[mt][kc][0]);
                        splitpk(acc[mt][2 * kc][2],     acc[mt][2 * kc][3],     ahi[mt][kc][1], alo[mt][kc][1]);
                        splitpk(acc[mt][2 * kc + 1][0], acc[mt][2 * kc + 1][1], ahi[mt][kc][2], alo[mt][kc][2]);
                        splitpk(acc[mt][2 * kc + 1][2], acc[mt][2 * kc + 1][3], ahi[mt][kc][3], alo[mt][kc][3]);
                    }
            }
        }

        // final 64 -> 5 projection
        float o[2][2][VOCAB];
        #pragma unroll
        for (int mt = 0; mt < 2; mt++)
            #pragma unroll
            for (int rr = 0; rr < 2; rr++) {
                o[mt][rr][0] = bo0; o[mt][rr][1] = bo1; o[mt][rr][2] = bo2;
                o[mt][rr][3] = bo3; o[mt][rr][4] = bo4;
            }
        #pragma unroll
        for (int nt = 0; nt < 8; nt++) {
            const int c0 = nt * 8 + tq * 2;
            const float4 wa = *(const float4*)(sWo8 + c0 * 8);
            const float  wa4 = sWo8[c0 * 8 + 4];
            const float4 wb = *(const float4*)(sWo8 + (c0 + 1) * 8);
            const float  wb4 = sWo8[(c0 + 1) * 8 + 4];
            #pragma unroll
            for (int mt = 0; mt < 2; mt++)
                #pragma unroll
                for (int rr = 0; rr < 2; rr++) {
                    const float h0 = acc[mt][nt][2 * rr], h1 = acc[mt][nt][2 * rr + 1];
                    o[mt][rr][0] = fmaf(h0, wa.x, fmaf(h1, wb.x, o[mt][rr][0]));
                    o[mt][rr][1] = fmaf(h0, wa.y, fmaf(h1, wb.y, o[mt][rr][1]));
                    o[mt][rr][2] = fmaf(h0, wa.z, fmaf(h1, wb.z, o[mt][rr][2]));
                    o[mt][rr][3] = fmaf(h0, wa.w, fmaf(h1, wb.w, o[mt][rr][3]));
                    o[mt][rr][4] = fmaf(h0, wa4,  fmaf(h1, wb4,  o[mt][rr][4]));
                }
        }
        #pragma unroll
        for (int mt = 0; mt < 2; mt++)
            #pragma unroll
            for (int rr = 0; rr < 2; rr++) {
                #pragma unroll
                for (int v = 0; v < VOCAB; v++) {
                    float t = o[mt][rr][v];
                    t += __shfl_xor_sync(0xFFFFFFFF, t, 1);
                    t += __shfl_xor_sync(0xFFFFFFFF, t, 2);
                    o[mt][rr][v] = t;
                }
                const int row = rowbase + mt * 16 + q + 8 * rr;
                float* op = out + (size_t)row * VOCAB;
                const float val = (tq & 2) ? ((tq & 1) ? o[mt][rr][3] : o[mt][rr][2])
                                           : ((tq & 1) ? o[mt][rr][1] : o[mt][rr][0]);
                op[tq] = val;
                if (tq == 0) op[4] = o[mt][rr][4];
            }
    }
}

// ---- tiled symmetrization ----
#define NT (S / 32)
#define TROW 160
#define TPAD 165
__global__ void symmetrize_tiled(float* __restrict__ out) {
    __shared__ float sA[32 * TPAD];
    __shared__ float sBt[32 * TPAD];
    int tp = blockIdx.x;
    const int b = blockIdx.y;
    int ti = 0;
    while (tp >= NT - ti) { tp -= NT - ti; ti++; }
    const int tj = ti + tp;
    const int bi = ti * 32, bj = tj * 32;
    const int tid = threadIdx.x;

    for (int f = tid; f < 32 * TROW; f += 256) {
        int r = f / TROW, c = f % TROW;
        sA [r * TPAD + c] = out[((size_t)(b * S + bi + r) * S + bj) * VOCAB + c];
        sBt[r * TPAD + c] = out[((size_t)(b * S + bj + r) * S + bi) * VOCAB + c];
    }
    __syncthreads();
    for (int f = tid; f < 32 * TROW; f += 256) {
        int r = f / TROW, c = f % TROW;
        int jj = c / VOCAB, v = c % VOCAB;
        float m = 0.5f * (sA[r * TPAD + c] + sBt[jj * TPAD + r * VOCAB + v]);
        out[((size_t)(b * S + bi + r) * S + bj) * VOCAB + c] = m;
    }
    for (int f = tid; f < 32 * TROW; f += 256) {
        int r = f / TROW, c = f % TROW;
        int jj = c / VOCAB, v = c % VOCAB;
        float m = 0.5f * (sBt[r * TPAD + c] + sA[jj * TPAD + r * VOCAB + v]);
        out[((size_t)(b * S + bj + r) * S + bi) * VOCAB + c] = m;
    }
}

extern "C" void kernel_launch(void* const* d_in, const int* in_sizes, int n_in,
                              void* d_out, int out_size) {
    const float* x    = (const float*)d_in[0];
    const float* W1   = (const float*)d_in[1];
    const float* b1   = (const float*)d_in[2];
    const float* W2   = (const float*)d_in[3];
    const float* b2   = (const float*)d_in[4];
    const float* W3   = (const float*)d_in[5];
    const float* b3   = (const float*)d_in[6];
    const float* ln_g = (const float*)d_in[7];
    const float* ln_b = (const float*)d_in[8];
    const float* Wo   = (const float*)d_in[9];
    const float* bo   = (const float*)d_in[10];
    float* out = (float*)d_out;

    static bool attr_set = false;
    if (!attr_set) {
        cudaFuncSetAttribute(mma_mlp_kernel,
                             cudaFuncAttributeMaxDynamicSharedMemorySize, SMEM_BYTES);
        attr_set = true;
    }

    prep_weights<<<(3 * 2 * 4 * 8 * 32 + 255) / 256, 256>>>(W1, W2, W3);
    mma_mlp_kernel<<<GRID_MAIN, TPB, SMEM_BYTES>>>(x, b1, b2, b3, ln_g, ln_b, Wo, bo, out);

    dim3 gsym(NT * (NT + 1) / 2, BATCH);
    symmetrize_tiled<<<gsym, 256>>>(out);
}

// round 6
// speedup vs baseline: 3.1295x; 1.0898x over previous
#include <cuda_runtime.h>
#include <cuda_bf16.h>
#include <math.h>
#include <stdint.h>

#define H 64
#define VOCAB 5
#define S 384
#define BATCH 8
#define NROWS (BATCH * S * S)     // 1,179,648
#define NTILES (NROWS / 128)      // 9216 tiles of 128 rows (32 per warp)
#define TPB 128
#define GRID_MAIN 296             // 148 SMs * 2 resident CTAs

// ---- dynamic smem layout ----
#define SM_BF    0
#define SM_WO8   49152
#define SM_BIAS  (SM_WO8 + 2048)
#define SMEM_BYTES (SM_BIAS + 768)   // 51968

// Pre-built B fragments for mma.m16n8k16.row.col (gamma-folded for layers 1,2)
__device__ uint2 g_bf[3][2][4][8][32];
// gamma/beta-folded biases and output weights
__device__ float g_bias2[64];
__device__ float g_bias3[64];
__device__ float g_wop[64 * 8];   // gamma-scaled Wo, padded to 8 cols
__device__ float g_bop[8];        // beta-folded bo

static __device__ __forceinline__ unsigned short bfu(__nv_bfloat16 h) {
    return __bfloat16_as_ushort(h);
}

// W fragments; layers 1,2 (W2,W3) are pre-scaled by ln_g along k (LN fold)
__global__ void prep_weights(const float* __restrict__ W1, const float* __restrict__ W2,
                             const float* __restrict__ W3, const float* __restrict__ ln_g) {
    int idx = blockIdx.x * blockDim.x + threadIdx.x;
    if (idx >= 3 * 2 * 4 * 8 * 32) return;
    int lane = idx & 31;
    int nt = (idx >> 5) & 7;
    int ks = (idx >> 8) & 3;
    int t  = (idx >> 10) & 1;
    int l  = idx >> 11;
    const float* W = (l == 0) ? W1 : (l == 1) ? W2 : W3;
    int n  = nt * 8 + (lane >> 2);
    int k0 = ks * 16 + (lane & 3) * 2;

    unsigned short e[4];
    int kk[4] = {k0, k0 + 1, k0 + 8, k0 + 9};
    for (int i = 0; i < 4; i++) {
        float w = W[kk[i] * H + n];
        if (l > 0) w *= ln_g[kk[i]];
        __nv_bfloat16 hi = __float2bfloat16_rn(w);
        if (t == 0) e[i] = bfu(hi);
        else        e[i] = bfu(__float2bfloat16_rn(w - __bfloat162float(hi)));
    }
    uint2 r;
    r.x = (uint32_t)e[0] | ((uint32_t)e[1] << 16);
    r.y = (uint32_t)e[2] | ((uint32_t)e[3] << 16);
    g_bf[l][t][ks][nt][lane] = r;
}

// folded biases: bias' = beta @ W + b ; Wo' = gamma (.) Wo ; bo' = beta @ Wo + bo
__global__ void prep_fold(const float* __restrict__ W2, const float* __restrict__ b2,
                          const float* __restrict__ W3, const float* __restrict__ b3,
                          const float* __restrict__ ln_g, const float* __restrict__ ln_b,
                          const float* __restrict__ Wo, const float* __restrict__ bo) {
    int tid = threadIdx.x;
    if (tid < 64) {
        float s = b2[tid];
        for (int k = 0; k < 64; k++) s = fmaf(ln_b[k], W2[k * H + tid], s);
        g_bias2[tid] = s;
    } else if (tid < 128) {
        int n = tid - 64;
        float s = b3[n];
        for (int k = 0; k < 64; k++) s = fmaf(ln_b[k], W3[k * H + n], s);
        g_bias3[n] = s;
    } else if (tid < 192) {
        int k = tid - 128;
        const float g = ln_g[k];
        for (int v = 0; v < 8; v++)
            g_wop[k * 8 + v] = (v < VOCAB) ? g * Wo[k * VOCAB + v] : 0.0f;
    } else if (tid < 200) {
        int v = tid - 192;
        float s = 0.0f;
        if (v < VOCAB) {
            s = bo[v];
            for (int k = 0; k < 64; k++) s = fmaf(ln_b[k], Wo[k * VOCAB + v], s);
        }
        g_bop[v] = s;
    }
}

// hi/lo bf16 split of a float pair via packed cvt: 6 ops
static __device__ __forceinline__ void splitpk(float a, float b, uint32_t& hp, uint32_t& lp) {
    __nv_bfloat162 h2 = __floats2bfloat162_rn(a, b);   // .x = a (low), .y = b (high)
    uint32_t u = *(uint32_t*)&h2;
    float ha = __uint_as_float(u << 16);
    float hb = __uint_as_float(u & 0xFFFF0000u);
    __nv_bfloat162 l2 = __floats2bfloat162_rn(a - ha, b - hb);
    hp = u;
    lp = *(uint32_t*)&l2;
}

// Branch-free exact-gelu (A&S 7.1.26 erf, abs err <= 1.5e-7)
static __device__ __forceinline__ float gelu_f(float v) {
    const float z  = fabsf(v) * 0.70710678118654752f;
    const float t  = __fdividef(1.0f, fmaf(0.3275911f, z, 1.0f));
    float p = fmaf(1.061405429f, t, -1.453152027f);
    p = fmaf(p, t, 1.421413741f);
    p = fmaf(p, t, -0.284496736f);
    p = fmaf(p, t, 0.254829592f);
    p = p * t;
    const float e  = __expf(-z * z);
    const float er = fmaf(-p, e, 1.0f);
    const float es = copysignf(er, v);
    const float hv = 0.5f * v;
    return fmaf(hv, es, hv);
}

#define MMA(d, a, bx, by)                                                              \
    asm volatile("mma.sync.aligned.m16n8k16.row.col.f32.bf16.bf16.f32 "                \
        "{%0,%1,%2,%3}, {%4,%5,%6,%7}, {%8,%9}, {%0,%1,%2,%3};"                        \
        : "+f"(d[0]), "+f"(d[1]), "+f"(d[2]), "+f"(d[3])                               \
        : "r"(a[0]), "r"(a[1]), "r"(a[2]), "r"(a[3]), "r"(bx), "r"(by))

__global__ __launch_bounds__(TPB, 2)
void mma_mlp_kernel(const float* __restrict__ x,
                    const float* __restrict__ b1,
                    float* __restrict__ out) {
    extern __shared__ __align__(16) unsigned char smem[];
    uint2*  sBF   = (uint2*)(smem + SM_BF);
    float*  sWo8  = (float*)(smem + SM_WO8);
    float*  sBias = (float*)(smem + SM_BIAS);

    const int tid  = threadIdx.x;
    const int lane = tid & 31;
    const int warp = tid >> 5;
    const int q    = lane >> 2;
    const int tq   = lane & 3;

    {
        const uint4* src = (const uint4*)g_bf;
        uint4* dst = (uint4*)(smem + SM_BF);
        #pragma unroll
        for (int i = tid; i < 49152 / 16; i += TPB) dst[i] = src[i];
    }
    for (int i = tid; i < H * 8; i += TPB) sWo8[i] = g_wop[i];
    if (tid < H) {
        sBias[tid] = b1[tid];
        sBias[64 + tid] = g_bias2[tid];
        sBias[128 + tid] = g_bias3[tid];
    }
    __syncthreads();

    const float bo0 = g_bop[0], bo1 = g_bop[1], bo2 = g_bop[2],
                bo3 = g_bop[3], bo4 = g_bop[4];

    for (int tile = blockIdx.x; tile < NTILES; tile += gridDim.x) {
        const int rowbase = tile * 128 + warp * 32;
        const float* xb = x + (size_t)rowbase * H;

        uint32_t ahi[2][4][4], alo[2][4][4];
        #pragma unroll
        for (int mt = 0; mt < 2; mt++)
            #pragma unroll
            for (int kc = 0; kc < 4; kc++)
                #pragma unroll
                for (int h2 = 0; h2 < 2; h2++)
                    #pragma unroll
                    for (int rr = 0; rr < 2; rr++) {
                        const float2 v = *(const float2*)(xb + (size_t)(mt * 16 + q + 8 * rr) * H
                                                          + kc * 16 + h2 * 8 + tq * 2);
                        splitpk(v.x, v.y, ahi[mt][kc][h2 * 2 + rr], alo[mt][kc][h2 * 2 + rr]);
                    }

        float acc[2][8][4];
        float rs[2][2], cc[2][2];   // rstd and -mu*rstd per (mt, rr)
        #pragma unroll
        for (int l = 0; l < 3; l++) {
            #pragma unroll
            for (int nt = 0; nt < 8; nt++) {
                const float2 bb = *(const float2*)(sBias + l * 64 + nt * 8 + tq * 2);
                #pragma unroll
                for (int mt = 0; mt < 2; mt++) {
                    acc[mt][nt][0] = bb.x; acc[mt][nt][1] = bb.y;
                    acc[mt][nt][2] = bb.x; acc[mt][nt][3] = bb.y;
                }
            }
            #pragma unroll
            for (int ks = 0; ks < 4; ks++) {
                #pragma unroll
                for (int nt = 0; nt < 8; nt++) {
                    const uint2 bh = sBF[(((l * 2 + 0) * 4 + ks) * 8 + nt) * 32 + lane];
                    const uint2 bl = sBF[(((l * 2 + 1) * 4 + ks) * 8 + nt) * 32 + lane];
                    MMA(acc[0][nt], ahi[0][ks], bh.x, bh.y);
                    MMA(acc[1][nt], ahi[1][ks], bh.x, bh.y);
                    MMA(acc[0][nt], alo[0][ks], bh.x, bh.y);
                    MMA(acc[1][nt], alo[1][ks], bh.x, bh.y);
                    MMA(acc[0][nt], ahi[0][ks], bl.x, bl.y);
                    MMA(acc[1][nt], ahi[1][ks], bl.x, bl.y);
                }
            }

            // gelu + LN statistics
            float s0[2][2] = {{0, 0}, {0, 0}}, s1[2][2] = {{0, 0}, {0, 0}};
            #pragma unroll
            for (int mt = 0; mt < 2; mt++)
                #pragma unroll
                for (int nt = 0; nt < 8; nt++)
                    #pragma unroll
                    for (int i = 0; i < 4; i++) {
                        const float g = gelu_f(acc[mt][nt][i]);
                        acc[mt][nt][i] = g;
                        s0[mt][i >> 1] += g;
                        s1[mt][i >> 1] += g * g;
                    }
            #pragma unroll
            for (int mt = 0; mt < 2; mt++)
                #pragma unroll
                for (int rr = 0; rr < 2; rr++) {
                    float a = s0[mt][rr], b = s1[mt][rr];
                    a += __shfl_xor_sync(0xFFFFFFFF, a, 1);
                    b += __shfl_xor_sync(0xFFFFFFFF, b, 1);
                    a += __shfl_xor_sync(0xFFFFFFFF, a, 2);
                    b += __shfl_xor_sync(0xFFFFFFFF, b, 2);
                    const float m = a * (1.0f / 64.0f);
                    const float var = b * (1.0f / 64.0f) - m * m;
                    const float r = rsqrtf(var + 1e-5f);
                    rs[mt][rr] = r;
                    cc[mt][rr] = -m * r;    // n = g*rstd + (-mu*rstd)
                }

            if (l < 2) {
                // fused LN-apply + split back into A fragments (gamma/beta folded downstream)
                #pragma unroll
                for (int mt = 0; mt < 2; mt++)
                    #pragma unroll
                    for (int kc = 0; kc < 4; kc++) {
                        const float n00 = fmaf(acc[mt][2 * kc][0],     rs[mt][0], cc[mt][0]);
                        const float n01 = fmaf(acc[mt][2 * kc][1],     rs[mt][0], cc[mt][0]);
                        const float n02 = fmaf(acc[mt][2 * kc][2],     rs[mt][1], cc[mt][1]);
                        const float n03 = fmaf(acc[mt][2 * kc][3],     rs[mt][1], cc[mt][1]);
                        const float n10 = fmaf(acc[mt][2 * kc + 1][0], rs[mt][0], cc[mt][0]);
                        const float n11 = fmaf(acc[mt][2 * kc + 1][1], rs[mt][0], cc[mt][0]);
                        const float n12 = fmaf(acc[mt][2 * kc + 1][2], rs[mt][1], cc[mt][1]);
                        const float n13 = fmaf(acc[mt][2 * kc + 1][3], rs[mt][1], cc[mt][1]);
                        splitpk(n00, n01, ahi[mt][kc][0], alo[mt][kc][0]);
                        splitpk(n02, n03, ahi[mt][kc][1], alo[mt][kc][1]);
                        splitpk(n10, n11, ahi[mt][kc][2], alo[mt][kc][2]);
                        splitpk(n12, n13, ahi[mt][kc][3], alo[mt][kc][3]);
                    }
            }
        }

        // final 64 -> 5 projection with inline LN apply (Wo is gamma-scaled, bo beta-folded)
        float o[2][2][VOCAB];
        #pragma unroll
        for (int mt = 0; mt < 2; mt++)
            #pragma unroll
            for (int rr = 0; rr < 2; rr++) {
                o[mt][rr][0] = bo0; o[mt][rr][1] = bo1; o[mt][rr][2] = bo2;
                o[mt][rr][3] = bo3; o[mt][rr][4] = bo4;
            }
        #pragma unroll
        for (int nt = 0; nt < 8; nt++) {
            const int c0 = nt * 8 + tq * 2;
            const float4 wa = *(const float4*)(sWo8 + c0 * 8);
            const float  wa4 = sWo8[c0 * 8 + 4];
            const float4 wb = *(const float4*)(sWo8 + (c0 + 1) * 8);
            const float  wb4 = sWo8[(c0 + 1) * 8 + 4];
            #pragma unroll
            for (int mt = 0; mt < 2; mt++)
                #pragma unroll
                for (int rr = 0; rr < 2; rr++) {
                    const float h0 = fmaf(acc[mt][nt][2 * rr],     rs[mt][rr], cc[mt][rr]);
                    const float h1 = fmaf(acc[mt][nt][2 * rr + 1], rs[mt][rr], cc[mt][rr]);
                    o[mt][rr][0] = fmaf(h0, wa.x, fmaf(h1, wb.x, o[mt][rr][0]));
                    o[mt][rr][1] = fmaf(h0, wa.y, fmaf(h1, wb.y, o[mt][rr][1]));
                    o[mt][rr][2] = fmaf(h0, wa.z, fmaf(h1, wb.z, o[mt][rr][2]));
                    o[mt][rr][3] = fmaf(h0, wa.w, fmaf(h1, wb.w, o[mt][rr][3]));
                    o[mt][rr][4] = fmaf(h0, wa4,  fmaf(h1, wb4,  o[mt][rr][4]));
                }
        }
        #pragma unroll
        for (int mt = 0; mt < 2; mt++)
            #pragma unroll
            for (int rr = 0; rr < 2; rr++) {
                #pragma unroll
                for (int v = 0; v < VOCAB; v++) {
                    float t = o[mt][rr][v];
                    t += __shfl_xor_sync(0xFFFFFFFF, t, 1);
                    t += __shfl_xor_sync(0xFFFFFFFF, t, 2);
                    o[mt][rr][v] = t;
                }
                const int row = rowbase + mt * 16 + q + 8 * rr;
                float* op = out + (size_t)row * VOCAB;
                const float val = (tq & 2) ? ((tq & 1) ? o[mt][rr][3] : o[mt][rr][2])
                                           : ((tq & 1) ? o[mt][rr][1] : o[mt][rr][0]);
                op[tq] = val;
                if (tq == 0) op[4] = o[mt][rr][4];
            }
    }
}

// ---- tiled symmetrization ----
#define NT (S / 32)
#define TROW 160
#define TPAD 165
__global__ void symmetrize_tiled(float* __restrict__ out) {
    __shared__ float sA[32 * TPAD];
    __shared__ float sBt[32 * TPAD];
    int tp = blockIdx.x;
    const int b = blockIdx.y;
    int ti = 0;
    while (tp >= NT - ti) { tp -= NT - ti; ti++; }
    const int tj = ti + tp;
    const int bi = ti * 32, bj = tj * 32;
    const int tid = threadIdx.x;

    for (int f = tid; f < 32 * TROW; f += 256) {
        int r = f / TROW, c = f % TROW;
        sA [r * TPAD + c] = out[((size_t)(b * S + bi + r) * S + bj) * VOCAB + c];
        sBt[r * TPAD + c] = out[((size_t)(b * S + bj + r) * S + bi) * VOCAB + c];
    }
    __syncthreads();
    for (int f = tid; f < 32 * TROW; f += 256) {
        int r = f / TROW, c = f % TROW;
        int jj = c / VOCAB, v = c % VOCAB;
        float m = 0.5f * (sA[r * TPAD + c] + sBt[jj * TPAD + r * VOCAB + v]);
        out[((size_t)(b * S + bi + r) * S + bj) * VOCAB + c] = m;
    }
    for (int f = tid; f < 32 * TROW; f += 256) {
        int r = f / TROW, c = f % TROW;
        int jj = c / VOCAB, v = c % VOCAB;
        float m = 0.5f * (sBt[r * TPAD + c] + sA[jj * TPAD + r * VOCAB + v]);
        out[((size_t)(b * S + bj + r) * S + bi) * VOCAB + c] = m;
    }
}

extern "C" void kernel_launch(void* const* d_in, const int* in_sizes, int n_in,
                              void* d_out, int out_size) {
    const float* x    = (const float*)d_in[0];
    const float* W1   = (const float*)d_in[1];
    const float* b1   = (const float*)d_in[2];
    const float* W2   = (const float*)d_in[3];
    const float* b2   = (const float*)d_in[4];
    const float* W3   = (const float*)d_in[5];
    const float* b3   = (const float*)d_in[6];
    const float* ln_g = (const float*)d_in[7];
    const float* ln_b = (const float*)d_in[8];
    const float* Wo   = (const float*)d_in[9];
    const float* bo   = (const float*)d_in[10];
    float* out = (float*)d_out;

    static bool attr_set = false;
    if (!attr_set) {
        cudaFuncSetAttribute(mma_mlp_kernel,
                             cudaFuncAttributeMaxDynamicSharedMemorySize, SMEM_BYTES);
        attr_set = true;
    }

    prep_weights<<<(3 * 2 * 4 * 8 * 32 + 255) / 256, 256>>>(W1, W2, W3, ln_g);
    prep_fold<<<1, 256>>>(W2, b2, W3, b3, ln_g, ln_b, Wo, bo);
    mma_mlp_kernel<<<GRID_MAIN, TPB, SMEM_BYTES>>>(x, b1, out);

    dim3 gsym(NT * (NT + 1) / 2, BATCH);
    symmetrize_tiled<<<gsym, 256>>>(out);
}